// round 4
// baseline (speedup 1.0000x reference)
#include <cuda_runtime.h>
#include <cuda_bf16.h>
#include <math.h>

#define N_NODES 100000
#define N_EDGES 1600000
#define HID     128
#define NGRAPH  256

// ---------------- scratch (device globals; no allocation anywhere) ---------
__device__ float g_A[(size_t)N_NODES * HID];      // h0 -> (layer2 agg) -> h2
__device__ float g_B[(size_t)N_NODES * HID];      // layer1 agg -> h1
__device__ float g_wT[2][2][HID * HID];           // [layer][rel=0/root=1], transposed
__device__ float g_pooled[NGRAPH * HID];
__device__ float g_counts[NGRAPH];

// ---------------- helpers --------------------------------------------------
__device__ __forceinline__ void red_add_v4(float* addr, float4 v) {
    asm volatile("red.global.add.v4.f32 [%0], {%1,%2,%3,%4};"
                 :: "l"(__cvta_generic_to_global(addr)),
                    "f"(v.x), "f"(v.y), "f"(v.z), "f"(v.w)
                 : "memory");
}

// ---------------- 0a. zero a node-feature buffer ---------------------------
// 12500 blocks x 256 threads x 1 float4 = 12.8M floats exactly
__global__ void zero_buf_kernel(int which)
{
    float4* p = (float4*)(which ? g_B : g_A);
    p[(size_t)blockIdx.x * 256 + threadIdx.x] = make_float4(0.f, 0.f, 0.f, 0.f);
}

// zero pooled sums + counts: 129 blocks x 256 = 33024 = 256*128 + 256 exactly
__global__ void zero_pool_kernel()
{
    int idx = blockIdx.x * 256 + threadIdx.x;
    if (idx < NGRAPH * HID) g_pooled[idx] = 0.f;
    else                    g_counts[idx - NGRAPH * HID] = 0.f;
}

// ---------------- 0b. transpose weights: wT[k][j] = w[j][k] ----------------
// grid (64, 4): y selects matrix, 64*256 = 16384 elements
__global__ void transpose_kernel(const float* __restrict__ w1r,
                                 const float* __restrict__ w1o,
                                 const float* __restrict__ w2r,
                                 const float* __restrict__ w2o)
{
    const float* src;
    switch (blockIdx.y) {
        case 0: src = w1r; break;
        case 1: src = w1o; break;
        case 2: src = w2r; break;
        default: src = w2o; break;
    }
    float* dst = &g_wT[blockIdx.y >> 1][blockIdx.y & 1][0];
    int idx = blockIdx.x * 256 + threadIdx.x;     // output index, coalesced write
    int k = idx >> 7, j = idx & 127;
    dst[idx] = src[j * 128 + k];
}

// ---------------- 1. embedding with max_norm=1 -----------------------------
// one warp per node; 12500 blocks x 8 warps = 100000 warps exactly
__global__ void embed_kernel(const int* __restrict__ x,
                             const float* __restrict__ emb_w)
{
    int node = (blockIdx.x * 256 + threadIdx.x) >> 5;
    int lane = threadIdx.x & 31;
    int idx  = x[node];
    float4 v = *(const float4*)&emb_w[(size_t)idx * HID + lane * 4];
    float ss = v.x * v.x + v.y * v.y + v.z * v.z + v.w * v.w;
    #pragma unroll
    for (int o = 16; o > 0; o >>= 1)
        ss += __shfl_xor_sync(0xffffffffu, ss, o);
    float scale = fminf(1.0f, 1.0f / (sqrtf(ss) + 1e-7f));
    v.x *= scale; v.y *= scale; v.z *= scale; v.w *= scale;
    *(float4*)&g_A[(size_t)node * HID + lane * 4] = v;
}

// ---------------- 2. per-edge gather * w -> scatter-add --------------------
// one warp per 2 edges; 100000 blocks x 8 warps x 2 = 1.6M edges exactly
__global__ void __launch_bounds__(256)
edge_kernel(const int* __restrict__ ei,
            const float* __restrict__ ew,
            int layer)
{
    const float* h = layer ? g_B : g_A;
    float*     agg = layer ? g_A : g_B;
    int warp = (blockIdx.x * 256 + threadIdx.x) >> 5;
    int lane = threadIdx.x & 31;
    int e0 = warp * 2;
    int e1 = e0 + 1;

    int   src0 = ei[e0],           src1 = ei[e1];
    int   dst0 = ei[N_EDGES + e0], dst1 = ei[N_EDGES + e1];
    float w0   = ew[e0],           w1   = ew[e1];

    float4 v0 = *(const float4*)&h[(size_t)src0 * HID + lane * 4];
    float4 v1 = *(const float4*)&h[(size_t)src1 * HID + lane * 4];
    v0.x *= w0; v0.y *= w0; v0.z *= w0; v0.w *= w0;
    v1.x *= w1; v1.y *= w1; v1.z *= w1; v1.w *= w1;
    red_add_v4(&agg[(size_t)dst0 * HID + lane * 4], v0);
    red_add_v4(&agg[(size_t)dst1 * HID + lane * 4], v1);
}

// ---------------- 3. node update: relu(agg@Wr^T + b + h@Wo^T) --------------
// 3125 blocks x 32 nodes (exact), 256 threads, 32KB static smem.
// layer0: agg=B, h=A, out=B(in-place). layer1: agg=A, h=B, out=A(in-place).
// In-place is safe: whole tile staged to smem before any global write.
__global__ void __launch_bounds__(256)
node_kernel(int layer, const float* __restrict__ bias)
{
    __shared__ float sA[32 * 128];
    __shared__ float sH[32 * 128];
    const float* agg = layer ? g_A : g_B;
    const float* h   = layer ? g_B : g_A;
    float*       out = layer ? g_A : g_B;
    const float* wTr = &g_wT[layer][0][0];
    const float* wTo = &g_wT[layer][1][0];

    size_t base = (size_t)blockIdx.x * 32;

    // stage tile: 32 nodes x 32 float4 each, 4 iters of 256 threads
    #pragma unroll
    for (int i = threadIdx.x; i < 32 * 32; i += 256) {
        int node = i >> 5, c4 = i & 31;
        ((float4*)sA)[i] = *(const float4*)&agg[(base + node) * HID + c4 * 4];
        ((float4*)sH)[i] = *(const float4*)&h  [(base + node) * HID + c4 * 4];
    }
    __syncthreads();

    int jq = threadIdx.x & 31;        // output quad: cols jq*4..+3
    int ng = threadIdx.x >> 5;        // node group: nodes ng*4..+3
    float4 b4 = *(const float4*)&bias[jq * 4];

    float acc[4][4];
    #pragma unroll
    for (int n = 0; n < 4; n++) {
        acc[n][0] = 0.f; acc[n][1] = 0.f; acc[n][2] = 0.f; acc[n][3] = 0.f;
    }

    #pragma unroll 4
    for (int k = 0; k < 128; k++) {
        float4 wr = __ldg((const float4*)&wTr[k * 128 + jq * 4]);
        float4 wo = __ldg((const float4*)&wTo[k * 128 + jq * 4]);
        #pragma unroll
        for (int n = 0; n < 4; n++) {
            float a  = sA[(ng * 4 + n) * 128 + k];
            float hh = sH[(ng * 4 + n) * 128 + k];
            acc[n][0] += a * wr.x + hh * wo.x;
            acc[n][1] += a * wr.y + hh * wo.y;
            acc[n][2] += a * wr.z + hh * wo.z;
            acc[n][3] += a * wr.w + hh * wo.w;
        }
    }

    #pragma unroll
    for (int n = 0; n < 4; n++) {
        float4 o;
        o.x = fmaxf(acc[n][0] + b4.x, 0.f);
        o.y = fmaxf(acc[n][1] + b4.y, 0.f);
        o.z = fmaxf(acc[n][2] + b4.z, 0.f);
        o.w = fmaxf(acc[n][3] + b4.w, 0.f);
        *(float4*)&out[(base + ng * 4 + n) * HID + jq * 4] = o;
    }
}

// ---------------- 4. mean pool (sums + counts) -----------------------------
// one warp per node; h2 lives in g_A
__global__ void pool_kernel(const int* __restrict__ batch)
{
    int node = (blockIdx.x * 256 + threadIdx.x) >> 5;
    int lane = threadIdx.x & 31;
    int g = batch[node];
    float4 v = *(const float4*)&g_A[(size_t)node * HID + lane * 4];
    red_add_v4(&g_pooled[(size_t)g * HID + lane * 4], v);
    if (lane == 0) atomicAdd(&g_counts[g], 1.0f);
}

// ---------------- 5. classifier + softmax ----------------------------------
__global__ void cls_kernel(const float* __restrict__ w1,  // [64][128]
                           const float* __restrict__ b1,  // [64]
                           const float* __restrict__ w2,  // [2][64]
                           const float* __restrict__ b2,  // [2]
                           float* __restrict__ out)       // [256][2]
{
    int g = blockIdx.x;
    int j = threadIdx.x;                 // 0..63
    __shared__ float p[128];
    __shared__ float z[64];
    float inv = 1.0f / fmaxf(g_counts[g], 1.0f);
    p[j]      = g_pooled[g * HID + j] * inv;
    p[j + 64] = g_pooled[g * HID + j + 64] * inv;
    __syncthreads();
    float acc = b1[j];
    #pragma unroll 4
    for (int k = 0; k < 128; k++)
        acc += p[k] * w1[j * 128 + k];
    z[j] = fmaxf(acc, 0.f);
    __syncthreads();
    if (j == 0) {
        float l0 = b2[0], l1 = b2[1];
        #pragma unroll 4
        for (int k = 0; k < 64; k++) {
            l0 += z[k] * w2[k];
            l1 += z[k] * w2[64 + k];
        }
        float m  = fmaxf(l0, l1);
        float e0 = expf(l0 - m), e1 = expf(l1 - m);
        float s  = e0 + e1;
        out[g * 2]     = e0 / s;
        out[g * 2 + 1] = e1 / s;
    }
}

// ---------------- launch: KERNEL LAUNCHES ONLY ------------------------------
extern "C" void kernel_launch(void* const* d_in, const int* in_sizes, int n_in,
                              void* d_out, int out_size)
{
    const int*   x      = (const int*)  d_in[0];
    const int*   ei     = (const int*)  d_in[1];
    const float* ew     = (const float*)d_in[2];
    const int*   batch  = (const int*)  d_in[3];
    const float* emb_w  = (const float*)d_in[4];
    const float* w1_rel = (const float*)d_in[5];
    const float* b1_rel = (const float*)d_in[6];
    const float* w1_root= (const float*)d_in[7];
    const float* w2_rel = (const float*)d_in[8];
    const float* b2_rel = (const float*)d_in[9];
    const float* w2_root= (const float*)d_in[10];
    const float* cls1_w = (const float*)d_in[11];
    const float* cls1_b = (const float*)d_in[12];
    const float* cls2_w = (const float*)d_in[13];
    const float* cls2_b = (const float*)d_in[14];
    float* out = (float*)d_out;

    // weight transposes (tiny)
    transpose_kernel<<<dim3(64, 4), 256>>>(w1_rel, w1_root, w2_rel, w2_root);

    // embedding -> A
    embed_kernel<<<12500, 256>>>(x, emb_w);

    // layer 1: agg in B, h1 written in-place into B
    zero_buf_kernel<<<12500, 256>>>(1);
    edge_kernel<<<100000, 256>>>(ei, ew, 0);
    node_kernel<<<3125, 256>>>(0, b1_rel);

    // layer 2: agg in A (h0 dead), h2 written in-place into A
    zero_buf_kernel<<<12500, 256>>>(0);
    edge_kernel<<<100000, 256>>>(ei, ew, 1);
    node_kernel<<<3125, 256>>>(1, b2_rel);

    // pooling
    zero_pool_kernel<<<129, 256>>>();
    pool_kernel<<<12500, 256>>>(batch);

    // classifier + softmax
    cls_kernel<<<NGRAPH, 64>>>(cls1_w, cls1_b, cls2_w, cls2_b, out);
}